// round 12
// baseline (speedup 1.0000x reference)
#include <cuda_runtime.h>
#include <math_constants.h>

// cummax along T for [B, T, H, C] = [16, 512, 64, 128] fp32.
//
// R10 = R7 (bench champion, 86.5us) with UNROLL 16 -> 32.
// Established model:
//  - DRAM% saturates at ~77% (~6.1 TB/s): mixed 50/50 R/W HBM ceiling.
//    28 KB/SM in flight -> 67%; 56 KB -> 75-77%; sustained 90+ KB (R9) -> 76.7%.
//  - Bench-vs-ncu gap tracks SM power: simple non-pipelined float4 sustains
//    the highest replay-loop clocks (R7 gap 4.9us vs R5/R9 gap 10-13us).
// So: keep the minimal-instruction float4 batch structure, halve loop
// overhead with UNROLL=32 (16 outer iterations), 112 KB/SM load-phase depth.

#define B_DIM 16
#define T_DIM 512
#define HC_DIM (64 * 128)            // 8192 floats per timestep
#define HC4 (HC_DIM / 4)             // 2048 float4 per timestep
#define UNROLL 32

__global__ __launch_bounds__(32)
void cummax_time_kernel_v4u32(const float4* __restrict__ in, float4* __restrict__ out) {
    const unsigned col4 = blockIdx.x * blockDim.x + threadIdx.x;   // 0..32767, exact

    const unsigned b      = col4 / HC4;
    const unsigned inner4 = col4 % HC4;

    const size_t base = (size_t)b * T_DIM * HC4 + inner4;
    const float4* __restrict__ p = in + base;
    float4* __restrict__       q = out + base;

    float mx = -CUDART_INF_F;
    float my = -CUDART_INF_F;
    float mz = -CUDART_INF_F;
    float mw = -CUDART_INF_F;

    // 16 outer iterations; 32 independent LDG.128 front-batched (512 B/thread
    // in flight), then 4 independent serial max chains, then 32 STG.128.
    #pragma unroll 1
    for (int tt = 0; tt < T_DIM; tt += UNROLL) {
        float4 v[UNROLL];
        #pragma unroll
        for (int i = 0; i < UNROLL; ++i) {
            v[i] = __ldcs(p + (size_t)i * HC4);      // streaming LDG.128
        }
        #pragma unroll
        for (int i = 0; i < UNROLL; ++i) {
            mx = fmaxf(mx, v[i].x);  v[i].x = mx;
            my = fmaxf(my, v[i].y);  v[i].y = my;
            mz = fmaxf(mz, v[i].z);  v[i].z = mz;
            mw = fmaxf(mw, v[i].w);  v[i].w = mw;
        }
        #pragma unroll
        for (int i = 0; i < UNROLL; ++i) {
            __stcs(q + (size_t)i * HC4, v[i]);       // streaming STG.128
        }
        p += (size_t)UNROLL * HC4;
        q += (size_t)UNROLL * HC4;
    }
}

extern "C" void kernel_launch(void* const* d_in, const int* in_sizes, int n_in,
                              void* d_out, int out_size) {
    const float4* in = (const float4*)d_in[0];
    float4* out = (float4*)d_out;

    const int total_cols4 = B_DIM * HC4;              // 32768
    const int threads = 32;
    const int blocks = total_cols4 / threads;         // 1024 -> 6.92 blocks/SM

    cummax_time_kernel_v4u32<<<blocks, threads>>>(in, out);
}

// round 13
// speedup vs baseline: 1.0545x; 1.0545x over previous
#include <cuda_runtime.h>
#include <math_constants.h>

// cummax along T for [B, T, H, C] = [16, 512, 64, 128] fp32.
//
// R12: float2 columns — the unexplored point on the (warps/SM, instr-count)
// tradeoff.
// Established model:
//   - DRAM% ceiling ~77% for this mixed R/W stream; in-flight beyond
//     ~56 KB/SM buys nothing (R7/R9/R10 all 75-77%).
//   - At equal in-flight, MORE warps -> higher DRAM% (R5: 27.7 warps, 77.2%
//     vs R7: 6.9 warps, 75.2%): more concurrent streams = smoother HBM
//     scheduling.
//   - High instruction count (R5, 4x) and high regs (R9/R10, 140+) both
//     hurt the bench replay loop.
// float2: 13.8 warps/SM, 2x R7 instructions, ~45 regs, same exact
// 1024-block / 6.92-per-SM wave balance, UNROLL=16 (56 KB/SM known-good).

#define B_DIM 16
#define T_DIM 512
#define HC_DIM (64 * 128)            // 8192 floats per timestep
#define HC2 (HC_DIM / 2)             // 4096 float2 per timestep
#define UNROLL 16

__global__ __launch_bounds__(64)
void cummax_time_kernel_v2(const float2* __restrict__ in, float2* __restrict__ out) {
    const unsigned col2 = blockIdx.x * blockDim.x + threadIdx.x;   // 0..65535, exact

    const unsigned b      = col2 / HC2;
    const unsigned inner2 = col2 % HC2;

    const size_t base = (size_t)b * T_DIM * HC2 + inner2;
    const float2* __restrict__ p = in + base;
    float2* __restrict__       q = out + base;

    float mx = -CUDART_INF_F;
    float my = -CUDART_INF_F;

    // 32 outer iterations; 16 independent LDG.64 front-batched
    // (128 B/thread in flight), 2 independent max chains, 16 STG.64.
    #pragma unroll 1
    for (int tt = 0; tt < T_DIM; tt += UNROLL) {
        float2 v[UNROLL];
        #pragma unroll
        for (int i = 0; i < UNROLL; ++i) {
            v[i] = __ldcs(p + (size_t)i * HC2);      // streaming LDG.64
        }
        #pragma unroll
        for (int i = 0; i < UNROLL; ++i) {
            mx = fmaxf(mx, v[i].x);  v[i].x = mx;
            my = fmaxf(my, v[i].y);  v[i].y = my;
        }
        #pragma unroll
        for (int i = 0; i < UNROLL; ++i) {
            __stcs(q + (size_t)i * HC2, v[i]);       // streaming STG.64
        }
        p += (size_t)UNROLL * HC2;
        q += (size_t)UNROLL * HC2;
    }
}

extern "C" void kernel_launch(void* const* d_in, const int* in_sizes, int n_in,
                              void* d_out, int out_size) {
    const float2* in = (const float2*)d_in[0];
    float2* out = (float2*)d_out;

    const int total_cols2 = B_DIM * HC2;              // 65536
    const int threads = 64;
    const int blocks = total_cols2 / threads;         // 1024 -> 6.92 blocks/SM

    cummax_time_kernel_v2<<<blocks, threads>>>(in, out);
}